// round 4
// baseline (speedup 1.0000x reference)
#include <cuda_runtime.h>
#include <math.h>

#define HID 2048
#define VOC 256
#define SEQ 2048
#define G3  (3 * HID)          // 6144

// ---- recurrence kernel geometry ----
#define RGRID     147          // ceil(2048/14); <= SM count -> co-resident
#define RJ        14           // h-indices per CTA
#define NROWS     42           // 3 gates * RJ
#define RTPB      512          // 16 warps
#define SMEM_ROWS 26           // weight rows resident in SMEM
#define RECUR_SMEM ((SMEM_ROWS * HID + HID + 64) * 4)

// ---- device scratch ----
__device__ float g_gi_enc[VOC * G3];
__device__ float g_gi_dec[VOC * G3];
__device__ float g_hbuf[2][HID];            // double-buffered hidden state
__device__ float g_dec_hs[(size_t)SEQ * HID];
__device__ unsigned int g_flag[RGRID];      // per-CTA monotone step flags

// ---- gpu-scope release/acquire helpers ----
__device__ __forceinline__ void st_release_gpu(unsigned* p, unsigned v) {
    asm volatile("st.release.gpu.u32 [%0], %1;" :: "l"(p), "r"(v) : "memory");
}
__device__ __forceinline__ unsigned ld_acquire_gpu(const unsigned* p) {
    unsigned v;
    asm volatile("ld.acquire.gpu.u32 %0, [%1];" : "=r"(v) : "l"(p) : "memory");
    return v;
}

// ============================================================
// C[M,N] = A[M,K] * B[N,K]^T + bias[N]   (fp32, 64x64 tile)
// ============================================================
__global__ __launch_bounds__(256) void gemm_nt(
    const float* __restrict__ A, const float* __restrict__ B,
    const float* __restrict__ bias, float* __restrict__ C,
    int M, int N, int K)
{
    __shared__ float As[16][68];
    __shared__ float Bs[16][68];

    const int tid = threadIdx.x;
    const int m0 = blockIdx.y * 64;
    const int n0 = blockIdx.x * 64;
    const int ml = tid >> 2;
    const int k4 = (tid & 3) << 2;
    const int ty = tid >> 4;
    const int tx = tid & 15;

    float acc[4][4] = {};

    for (int kb = 0; kb < K; kb += 16) {
        float4 a = *(const float4*)&A[(size_t)(m0 + ml) * K + kb + k4];
        float4 b = *(const float4*)&B[(size_t)(n0 + ml) * K + kb + k4];
        As[k4 + 0][ml] = a.x; As[k4 + 1][ml] = a.y;
        As[k4 + 2][ml] = a.z; As[k4 + 3][ml] = a.w;
        Bs[k4 + 0][ml] = b.x; Bs[k4 + 1][ml] = b.y;
        Bs[k4 + 2][ml] = b.z; Bs[k4 + 3][ml] = b.w;
        __syncthreads();
#pragma unroll
        for (int k = 0; k < 16; k++) {
            float4 av = *(const float4*)&As[k][ty << 2];
            float4 bv = *(const float4*)&Bs[k][tx << 2];
            acc[0][0] += av.x * bv.x; acc[0][1] += av.x * bv.y;
            acc[0][2] += av.x * bv.z; acc[0][3] += av.x * bv.w;
            acc[1][0] += av.y * bv.x; acc[1][1] += av.y * bv.y;
            acc[1][2] += av.y * bv.z; acc[1][3] += av.y * bv.w;
            acc[2][0] += av.z * bv.x; acc[2][1] += av.z * bv.y;
            acc[2][2] += av.z * bv.z; acc[2][3] += av.z * bv.w;
            acc[3][0] += av.w * bv.x; acc[3][1] += av.w * bv.y;
            acc[3][2] += av.w * bv.z; acc[3][3] += av.w * bv.w;
        }
        __syncthreads();
    }

#pragma unroll
    for (int i = 0; i < 4; i++) {
        const int m = m0 + (ty << 2) + i;
#pragma unroll
        for (int j = 0; j < 4; j++) {
            const int n = n0 + (tx << 2) + j;
            C[(size_t)m * N + n] = acc[i][j] + bias[n];
        }
    }
}

// ============================================================
// Reset: zero h buffer 0 and the per-CTA flags (runs each launch
// so graph replays start from a clean state).
// ============================================================
__global__ void reset_kernel()
{
    const int tid = threadIdx.x;
    float4* b0 = (float4*)g_hbuf[0];
    for (int i = tid; i < HID / 4; i += 256)
        b0[i] = make_float4(0.f, 0.f, 0.f, 0.f);
    for (int i = tid; i < RGRID; i += 256)
        g_flag[i] = 0u;
}

// ============================================================
// Persistent GRU recurrence: 147 co-resident CTAs x 512 threads.
// CTA c owns h-indices [14c, 14c+14). Rows lr in [0,42):
//   lr 0..15   -> SMEM slots 0..15
//   lr 16..31  -> registers (one row per warp, 64 regs/lane)
//   lr 32..41  -> SMEM slots 16..25
// Per step: one __ldcg float4/thread stages h; 16 warps do fp32
// dots; warp0 computes gates, publishes h via release-store flag;
// warp0 polls all 147 flags with acquire loads. 3 syncthreads/step.
// ============================================================
__global__ __launch_bounds__(RTPB, 1) void recur_kernel(
    const int* __restrict__ inputs, const int* __restrict__ targets,
    const float* __restrict__ enc_w_hh, const float* __restrict__ enc_b_hh,
    const float* __restrict__ dec_w_hh, const float* __restrict__ dec_b_hh)
{
    extern __shared__ float smem[];
    float* sw  = smem;                       // [26][2048]
    float* shh = sw + SMEM_ROWS * HID;       // [2048]
    float* sgh = shh + HID;                  // [48]

    const int tid   = threadIdx.x;
    const int w     = tid >> 5;
    const int lane  = tid & 31;
    const int cta   = blockIdx.x;
    const int jbase = cta * RJ;
    const int jg    = jbase + lane;          // valid for lane < 14

    float4 wreg[16];

    for (int phase = 0; phase < 2; phase++) {
        const float* Whh    = phase ? dec_w_hh : enc_w_hh;
        const float* Bhh    = phase ? dec_b_hh : enc_b_hh;
        const float* gi_tab = phase ? g_gi_dec : g_gi_enc;
        const int    tgt1   = __ldg(&targets[1]);

        // ---- SMEM-resident weight rows ----
        for (int s = 0; s < SMEM_ROWS; s++) {
            const int lr   = (s < 16) ? s : s + 16;
            const int gate = lr / RJ;
            const int jr   = jbase + (lr % RJ);
            if (jr < HID) {
                const float4* src = (const float4*)(Whh + (size_t)(gate * HID + jr) * HID);
                float4* dst = (float4*)(sw + s * HID);
                for (int idx = tid; idx < HID / 4; idx += RTPB) dst[idx] = src[idx];
            } else {
                for (int idx = tid; idx < HID; idx += RTPB) sw[s * HID + idx] = 0.f;
            }
        }
        // ---- register-resident row (lr = w + 16) ----
        {
            const int lr   = w + 16;
            const int gate = lr / RJ;
            const int jr   = jbase + (lr % RJ);
            if (jr < HID) {
                const float4* src = (const float4*)(Whh + (size_t)(gate * HID + jr) * HID);
#pragma unroll
                for (int i = 0; i < 16; i++) wreg[i] = src[i * 32 + lane];
            } else {
#pragma unroll
                for (int i = 0; i < 16; i++) wreg[i] = make_float4(0.f, 0.f, 0.f, 0.f);
            }
        }
        // ---- per-lane gate biases (warp0 lanes < 14) ----
        float b_r = 0.f, b_z = 0.f, b_n = 0.f;
        if (w == 0 && lane < RJ && jg < HID) {
            b_r = __ldg(&Bhh[jg]);
            b_z = __ldg(&Bhh[HID + jg]);
            b_n = __ldg(&Bhh[2 * HID + jg]);
        }

        for (int t = 0; t < SEQ; t++) {
            const int s = phase * SEQ + t;

            __syncthreads();                             // #1: step entry

            // ---- stage h(s-1): one float4 per thread, L2-only ----
            float4* dst = (float4*)shh;
            if (s == 0) {
                dst[tid] = make_float4(0.f, 0.f, 0.f, 0.f);
            } else {
                dst[tid] = __ldcg(((const float4*)g_hbuf[s & 1]) + tid);
            }

            // ---- prefetch gi into registers (warp0 gate lanes) ----
            float gi_r = 0.f, gi_z = 0.f, gi_n = 0.f;
            if (w == 0 && lane < RJ && jg < HID) {
                const int tok = phase ? (t == 0 ? 0 : tgt1) : __ldg(&inputs[t]);
                const float* gp = gi_tab + (size_t)tok * G3;
                gi_r = __ldg(&gp[jg]);
                gi_z = __ldg(&gp[HID + jg]);
                gi_n = __ldg(&gp[2 * HID + jg]);
            }
            __syncthreads();                             // #2: shh ready

            // ---- dots: warp w -> rows {w (SMEM), w+16 (RF), w+32 (SMEM)} ----
            {
                const float4* hv = (const float4*)shh;
                const float4* pa = (const float4*)(sw + w * HID);
                const float4* pc = (const float4*)(sw + (w + 16) * HID);
                float4 aA = make_float4(0.f, 0.f, 0.f, 0.f);
                float4 aB = aA, aC = aA;
#pragma unroll
                for (int i = 0; i < 16; i++) {
                    const int n = (i << 5) + lane;
                    float4 h4 = hv[n];
                    float4 x  = pa[n];
                    aA.x += x.x * h4.x; aA.y += x.y * h4.y;
                    aA.z += x.z * h4.z; aA.w += x.w * h4.w;
                    float4 y = wreg[i];
                    aB.x += y.x * h4.x; aB.y += y.y * h4.y;
                    aB.z += y.z * h4.z; aB.w += y.w * h4.w;
                    if (w < 10) {
                        float4 zz = pc[n];
                        aC.x += zz.x * h4.x; aC.y += zz.y * h4.y;
                        aC.z += zz.z * h4.z; aC.w += zz.w * h4.w;
                    }
                }
                float sA = (aA.x + aA.y) + (aA.z + aA.w);
                float sB = (aB.x + aB.y) + (aB.z + aB.w);
                float sC = (aC.x + aC.y) + (aC.z + aC.w);
#pragma unroll
                for (int o = 16; o > 0; o >>= 1) {
                    sA += __shfl_down_sync(0xffffffffu, sA, o);
                    sB += __shfl_down_sync(0xffffffffu, sB, o);
                    sC += __shfl_down_sync(0xffffffffu, sC, o);
                }
                if (lane == 0) {
                    sgh[w]      = sA;
                    sgh[w + 16] = sB;
                    if (w < 10) sgh[w + 32] = sC;
                }
            }
            __syncthreads();                             // #3: sgh ready

            // ---- warp0: gates + publish + chip-wide flag barrier ----
            if (w == 0) {
                if (lane < RJ && jg < HID) {
                    const float ghr = sgh[lane]          + b_r;
                    const float ghz = sgh[RJ + lane]     + b_z;
                    const float ghn = sgh[2 * RJ + lane] + b_n;
                    const float r  = 1.f / (1.f + expf(-(gi_r + ghr)));
                    const float z  = 1.f / (1.f + expf(-(gi_z + ghz)));
                    const float n_ = tanhf(gi_n + r * ghn);
                    const float hn = (1.f - z) * n_ + z * shh[jg];
                    g_hbuf[(s + 1) & 1][jg] = hn;
                    if (phase) g_dec_hs[(size_t)t * HID + jg] = hn;
                }
                __syncwarp();
                if (lane == 0) st_release_gpu(&g_flag[cta], (unsigned)(s + 1));

                // poll all 147 flags (5 per lane, acquire loads)
                const unsigned need = (unsigned)(s + 1);
                bool mine;
                do {
                    mine = true;
#pragma unroll
                    for (int k = 0; k < 5; k++) {
                        const int idx = lane + 32 * k;
                        if (idx < RGRID)
                            if (ld_acquire_gpu(&g_flag[idx]) < need) mine = false;
                    }
                } while (!__all_sync(0xffffffffu, mine));
            }
            // other warps run straight into next step's sync #1
        }
    }
}

// ============================================================
// Launch: gi tables (2 GEMMs) -> reset -> persistent recurrence
//         -> output projection GEMM.
// ============================================================
extern "C" void kernel_launch(void* const* d_in, const int* in_sizes, int n_in,
                              void* d_out, int out_size)
{
    const int*   inputs   = (const int*)d_in[0];
    const int*   targets  = (const int*)d_in[1];
    const float* emb      = (const float*)d_in[2];
    const float* enc_w_ih = (const float*)d_in[3];
    const float* enc_w_hh = (const float*)d_in[4];
    const float* enc_b_ih = (const float*)d_in[5];
    const float* enc_b_hh = (const float*)d_in[6];
    const float* dec_w_ih = (const float*)d_in[7];
    const float* dec_w_hh = (const float*)d_in[8];
    const float* dec_b_ih = (const float*)d_in[9];
    const float* dec_b_hh = (const float*)d_in[10];
    const float* fc_w     = (const float*)d_in[11];
    const float* fc_b     = (const float*)d_in[12];
    float* out = (float*)d_out;

    float *gi_enc_p, *gi_dec_p, *dec_hs_p;
    cudaGetSymbolAddress((void**)&gi_enc_p, g_gi_enc);
    cudaGetSymbolAddress((void**)&gi_dec_p, g_gi_dec);
    cudaGetSymbolAddress((void**)&dec_hs_p, g_dec_hs);
    cudaFuncSetAttribute(recur_kernel,
                         cudaFuncAttributeMaxDynamicSharedMemorySize, RECUR_SMEM);

    dim3 tb(256);
    gemm_nt<<<dim3(G3 / 64, VOC / 64), tb>>>(emb, enc_w_ih, enc_b_ih,
                                             gi_enc_p, VOC, G3, HID);
    gemm_nt<<<dim3(G3 / 64, VOC / 64), tb>>>(emb, dec_w_ih, dec_b_ih,
                                             gi_dec_p, VOC, G3, HID);
    reset_kernel<<<1, 256>>>();
    recur_kernel<<<RGRID, RTPB, RECUR_SMEM>>>(inputs, targets,
                                              enc_w_hh, enc_b_hh,
                                              dec_w_hh, dec_b_hh);
    gemm_nt<<<dim3(VOC / 64, SEQ / 64), tb>>>(dec_hs_p, fc_w, fc_b,
                                              out, SEQ, VOC, HID);
}